// round 1
// baseline (speedup 1.0000x reference)
#include <cuda_runtime.h>
#include <cuda_bf16.h>
#include <math.h>

// ---------------------------------------------------------------------------
// Problem constants
// ---------------------------------------------------------------------------
#define BATCH     2
#define SEQ       2048
#define DMODEL    1024
#define FFN_DIM   4096
#define NHEADS    8
#define HEAD_DIM  128
#define RL        4
#define LN_EPS    1e-5f

#define ROWS      (BATCH * SEQ)              // 4096
#define BLD       (BATCH * SEQ * DMODEL)     // 4,194,304
#define HEAD_BLK  (SEQ * HEAD_DIM)           // 262,144  (per-z stride in q/k/v)
#define NBH       (BATCH * NHEADS)           // 16
#define LL        (SEQ * SEQ)                // 4,194,304 per head

// ---------------------------------------------------------------------------
// Scratch (static device globals -- no allocation at runtime)
// ---------------------------------------------------------------------------
__device__ float g_q  [BLD];
__device__ float g_k  [BLD];
__device__ float g_v  [BLD];
__device__ float g_sc [(size_t)NBH * LL];    // 256 MB scores / attn (in place)
__device__ float g_ctx[BLD];
__device__ float g_hsa[BLD];
__device__ float g_h1 [BLD];
__device__ float g_mid[(size_t)ROWS * FFN_DIM]; // 64 MB
__device__ float g_hf [BLD];
__device__ float g_rq [ROWS * RL];
__device__ float g_rk [ROWS * RL];

// ---------------------------------------------------------------------------
// Generic tiled SGEMM: C = alpha * A @ B (+ score-bias) (+ bias) (+ relu)
// A: [M,K] row-major, B: [K,N] row-major, C: [M,N] row-major.
// Batched via blockIdx.z with element strides sA, sB, sC.
// All M % 128 == 0, N % 128 == 0, K % 16 == 0 for this problem -> no guards.
// ---------------------------------------------------------------------------
#define BM 128
#define BN 128
#define BK 16

template<bool BIAS, bool RELU, bool SCORE>
__global__ void __launch_bounds__(256, 2)
gemm_kernel(const float* __restrict__ A, const float* __restrict__ Bm,
            float* __restrict__ C,
            int M, int N, int K,
            long sA, long sB, long sC,
            const float* __restrict__ bias,
            const float* __restrict__ rq, const float* __restrict__ rk,
            float alpha)
{
    __shared__ float As[BK][BM];
    __shared__ float Bs[BK][BN];

    const int z = blockIdx.z;
    A  += (long)z * sA;
    Bm += (long)z * sB;
    C  += (long)z * sC;

    const float* rqb = nullptr;
    const float* rkb = nullptr;
    if (SCORE) {
        const int b = z >> 3;                 // z = 8*b + head
        rqb = rq + (long)b * M * RL;          // [M,4]
        rkb = rk + (long)b * RL * N;          // [4,N] (contiguous reinterpretation)
    }

    const int bm  = blockIdx.y * BM;
    const int bn  = blockIdx.x * BN;
    const int tid = threadIdx.x;              // 256 threads
    const int tr  = tid >> 4;                 // 0..15
    const int tc  = tid & 15;                 // 0..15

    float acc[8][8];
#pragma unroll
    for (int i = 0; i < 8; i++)
#pragma unroll
        for (int j = 0; j < 8; j++) acc[i][j] = 0.f;

    for (int k0 = 0; k0 < K; k0 += BK) {
        // ---- load A tile (BM x BK), store transposed into As[BK][BM]
#pragma unroll
        for (int i = 0; i < 2; i++) {
            int lin = tid + i * 256;          // 0..511
            int row = lin >> 2;               // 0..127
            int c4  = (lin & 3) * 4;          // 0,4,8,12
            float4 va = *reinterpret_cast<const float4*>(
                &A[(long)(bm + row) * K + k0 + c4]);
            As[c4 + 0][row] = va.x;
            As[c4 + 1][row] = va.y;
            As[c4 + 2][row] = va.z;
            As[c4 + 3][row] = va.w;
        }
        // ---- load B tile (BK x BN)
#pragma unroll
        for (int i = 0; i < 2; i++) {
            int lin = tid + i * 256;
            int row = lin >> 5;               // 0..15
            int c4  = (lin & 31) * 4;         // 0..124
            *reinterpret_cast<float4*>(&Bs[row][c4]) =
                *reinterpret_cast<const float4*>(
                    &Bm[(long)(k0 + row) * N + bn + c4]);
        }
        __syncthreads();

#pragma unroll
        for (int kk = 0; kk < BK; kk++) {
            float4 a0 = *reinterpret_cast<const float4*>(&As[kk][tr * 8]);
            float4 a1 = *reinterpret_cast<const float4*>(&As[kk][tr * 8 + 4]);
            float4 b0 = *reinterpret_cast<const float4*>(&Bs[kk][tc * 8]);
            float4 b1 = *reinterpret_cast<const float4*>(&Bs[kk][tc * 8 + 4]);
            float ar[8] = {a0.x, a0.y, a0.z, a0.w, a1.x, a1.y, a1.z, a1.w};
            float br[8] = {b0.x, b0.y, b0.z, b0.w, b1.x, b1.y, b1.z, b1.w};
#pragma unroll
            for (int i = 0; i < 8; i++)
#pragma unroll
                for (int j = 0; j < 8; j++)
                    acc[i][j] = fmaf(ar[i], br[j], acc[i][j]);
        }
        __syncthreads();
    }

    // ---- epilogue
#pragma unroll
    for (int i = 0; i < 8; i++) {
        const int r = bm + tr * 8 + i;
        float q0 = 0.f, q1 = 0.f, q2 = 0.f, q3 = 0.f;
        if (SCORE) {
            q0 = rqb[r * RL + 0]; q1 = rqb[r * RL + 1];
            q2 = rqb[r * RL + 2]; q3 = rqb[r * RL + 3];
        }
        float out[8];
#pragma unroll
        for (int j = 0; j < 8; j++) {
            const int c = bn + tc * 8 + j;
            float val = acc[i][j] * alpha;
            if (SCORE) {
                float bsum = q0 * rkb[c] + q1 * rkb[N + c]
                           + q2 * rkb[2 * N + c] + q3 * rkb[3 * N + c];
                val += 0.5f * bsum;
            }
            if (BIAS) val += bias[c];
            if (RELU) val = fmaxf(val, 0.f);
            out[j] = val;
        }
        float4* cp = reinterpret_cast<float4*>(&C[(long)r * N + bn + tc * 8]);
        cp[0] = make_float4(out[0], out[1], out[2], out[3]);
        cp[1] = make_float4(out[4], out[5], out[6], out[7]);
    }
}

// ---------------------------------------------------------------------------
// Tiny rank-4 projections: rq = rh @ Wrq, rk = rh @ Wrk   (rows = B*L)
// ---------------------------------------------------------------------------
__global__ void rproj_kernel(const float* __restrict__ rh,
                             const float* __restrict__ Wrk,
                             const float* __restrict__ Wrq,
                             float* __restrict__ rk, float* __restrict__ rq,
                             int n)
{
    int i = blockIdx.x * blockDim.x + threadIdx.x;
    if (i >= n) return;
    float x0 = rh[i * 4 + 0], x1 = rh[i * 4 + 1];
    float x2 = rh[i * 4 + 2], x3 = rh[i * 4 + 3];
#pragma unroll
    for (int j = 0; j < 4; j++) {
        rk[i * 4 + j] = x0 * Wrk[j] + x1 * Wrk[4 + j] + x2 * Wrk[8 + j] + x3 * Wrk[12 + j];
        rq[i * 4 + j] = x0 * Wrq[j] + x1 * Wrq[4 + j] + x2 * Wrq[8 + j] + x3 * Wrq[12 + j];
    }
}

// ---------------------------------------------------------------------------
// Row softmax over SEQ=2048 elements. One block (256 thr) per row, in place.
// ---------------------------------------------------------------------------
__global__ void __launch_bounds__(256)
softmax_kernel(float* __restrict__ S)
{
    float* p = S + (size_t)blockIdx.x * SEQ;
    const int tid = threadIdx.x;
    __shared__ float red[8];

    float v[8];
    float m = -INFINITY;
#pragma unroll
    for (int i = 0; i < 8; i++) {
        v[i] = p[tid + i * 256];
        m = fmaxf(m, v[i]);
    }
    // block max
#pragma unroll
    for (int o = 16; o > 0; o >>= 1) m = fmaxf(m, __shfl_xor_sync(0xffffffffu, m, o));
    if ((tid & 31) == 0) red[tid >> 5] = m;
    __syncthreads();
    m = red[0];
#pragma unroll
    for (int w = 1; w < 8; w++) m = fmaxf(m, red[w]);

    float s = 0.f;
#pragma unroll
    for (int i = 0; i < 8; i++) {
        v[i] = __expf(v[i] - m);
        s += v[i];
    }
#pragma unroll
    for (int o = 16; o > 0; o >>= 1) s += __shfl_xor_sync(0xffffffffu, s, o);
    __syncthreads();
    if ((tid & 31) == 0) red[tid >> 5] = s;
    __syncthreads();
    s = red[0];
#pragma unroll
    for (int w = 1; w < 8; w++) s += red[w];
    const float inv = 1.f / s;
#pragma unroll
    for (int i = 0; i < 8; i++) p[tid + i * 256] = v[i] * inv;
}

// ---------------------------------------------------------------------------
// LayerNorm over D=1024 of (x + y). One block (256 thr) per row.
// ---------------------------------------------------------------------------
__global__ void __launch_bounds__(256)
ln_kernel(const float* __restrict__ x, const float* __restrict__ y,
          const float* __restrict__ g, const float* __restrict__ b,
          float* __restrict__ out)
{
    const size_t base = (size_t)blockIdx.x * DMODEL;
    const int tid = threadIdx.x;
    __shared__ float rs[8], rs2[8];

    float v[4];
    float s = 0.f, s2 = 0.f;
#pragma unroll
    for (int i = 0; i < 4; i++) {
        int c = tid + i * 256;
        v[i] = x[base + c] + y[base + c];
        s  += v[i];
        s2 += v[i] * v[i];
    }
#pragma unroll
    for (int o = 16; o > 0; o >>= 1) {
        s  += __shfl_xor_sync(0xffffffffu, s,  o);
        s2 += __shfl_xor_sync(0xffffffffu, s2, o);
    }
    if ((tid & 31) == 0) { rs[tid >> 5] = s; rs2[tid >> 5] = s2; }
    __syncthreads();
    s = 0.f; s2 = 0.f;
#pragma unroll
    for (int w = 0; w < 8; w++) { s += rs[w]; s2 += rs2[w]; }
    const float mean = s * (1.f / DMODEL);
    const float var  = s2 * (1.f / DMODEL) - mean * mean;
    const float rstd = rsqrtf(var + LN_EPS);
#pragma unroll
    for (int i = 0; i < 4; i++) {
        int c = tid + i * 256;
        out[base + c] = (v[i] - mean) * rstd * g[c] + b[c];
    }
}

// ---------------------------------------------------------------------------
// Launch
// ---------------------------------------------------------------------------
extern "C" void kernel_launch(void* const* d_in, const int* in_sizes, int n_in,
                              void* d_out, int out_size)
{
    const float* h   = (const float*)d_in[0];
    const float* rh  = (const float*)d_in[1];
    const float* Wq  = (const float*)d_in[2];
    const float* Wk  = (const float*)d_in[3];
    const float* Wv  = (const float*)d_in[4];
    const float* Wo  = (const float*)d_in[5];
    const float* Wrk = (const float*)d_in[6];
    const float* Wrq = (const float*)d_in[7];
    const float* W1  = (const float*)d_in[8];
    const float* b1  = (const float*)d_in[9];
    const float* W2  = (const float*)d_in[10];
    const float* b2  = (const float*)d_in[11];
    const float* g1  = (const float*)d_in[12];
    const float* be1 = (const float*)d_in[13];
    const float* g2  = (const float*)d_in[14];
    const float* be2 = (const float*)d_in[15];
    float* out = (float*)d_out;

    float *q, *k, *v, *sc, *ctx, *hsa, *h1, *mid, *hf, *prq, *prk;
    cudaGetSymbolAddress((void**)&q,   g_q);
    cudaGetSymbolAddress((void**)&k,   g_k);
    cudaGetSymbolAddress((void**)&v,   g_v);
    cudaGetSymbolAddress((void**)&sc,  g_sc);
    cudaGetSymbolAddress((void**)&ctx, g_ctx);
    cudaGetSymbolAddress((void**)&hsa, g_hsa);
    cudaGetSymbolAddress((void**)&h1,  g_h1);
    cudaGetSymbolAddress((void**)&mid, g_mid);
    cudaGetSymbolAddress((void**)&hf,  g_hf);
    cudaGetSymbolAddress((void**)&prq, g_rq);
    cudaGetSymbolAddress((void**)&prk, g_rk);

    const float inv_sqrt_hd = 0.08838834764831845f; // 1/sqrt(128)

    dim3 blk(256);

    // QKV projections: [4096,1024] @ [1024,1024]
    {
        dim3 grid(DMODEL / BN, ROWS / BM, 1);
        gemm_kernel<false, false, false><<<grid, blk>>>(
            h, Wq, q, ROWS, DMODEL, DMODEL, 0, 0, 0, nullptr, nullptr, nullptr, 1.f);
        gemm_kernel<false, false, false><<<grid, blk>>>(
            h, Wk, k, ROWS, DMODEL, DMODEL, 0, 0, 0, nullptr, nullptr, nullptr, 1.f);
        gemm_kernel<false, false, false><<<grid, blk>>>(
            h, Wv, v, ROWS, DMODEL, DMODEL, 0, 0, 0, nullptr, nullptr, nullptr, 1.f);
    }

    // rank-4 projections
    rproj_kernel<<<(ROWS + 255) / 256, 256>>>(rh, Wrk, Wrq, prk, prq, ROWS);

    // scores: per z (16), Qh[2048,128] @ Kt[128,2048] * 1/sqrt(hd) + 0.5*rq·rk
    {
        dim3 grid(SEQ / BN, SEQ / BM, NBH);
        gemm_kernel<false, false, true><<<grid, blk>>>(
            q, k, sc, SEQ, SEQ, HEAD_DIM,
            HEAD_BLK, HEAD_BLK, (long)LL,
            nullptr, prq, prk, inv_sqrt_hd);
    }

    // softmax over rows
    softmax_kernel<<<NBH * SEQ, blk>>>(sc);

    // context: attn[2048,2048] @ V[2048,128] -> contiguous (n,l,d) == reshape(B,L,D)
    {
        dim3 grid(HEAD_DIM / BN, SEQ / BM, NBH);
        gemm_kernel<false, false, false><<<grid, blk>>>(
            sc, v, ctx, SEQ, HEAD_DIM, SEQ,
            (long)LL, HEAD_BLK, HEAD_BLK,
            nullptr, nullptr, nullptr, 1.f);
    }

    // output projection
    {
        dim3 grid(DMODEL / BN, ROWS / BM, 1);
        gemm_kernel<false, false, false><<<grid, blk>>>(
            ctx, Wo, hsa, ROWS, DMODEL, DMODEL, 0, 0, 0, nullptr, nullptr, nullptr, 1.f);
    }

    // h1 = LN(hsa + h)
    ln_kernel<<<ROWS, blk>>>(hsa, h, g1, be1, h1);

    // mid = relu(h1 @ W1 + b1)
    {
        dim3 grid(FFN_DIM / BN, ROWS / BM, 1);
        gemm_kernel<true, true, false><<<grid, blk>>>(
            h1, W1, mid, ROWS, FFN_DIM, DMODEL, 0, 0, 0, b1, nullptr, nullptr, 1.f);
    }

    // hf = mid @ W2 + b2
    {
        dim3 grid(DMODEL / BN, ROWS / BM, 1);
        gemm_kernel<true, false, false><<<grid, blk>>>(
            mid, W2, hf, ROWS, DMODEL, FFN_DIM, 0, 0, 0, b2, nullptr, nullptr, 1.f);
    }

    // out = LN(h1 + hf)
    ln_kernel<<<ROWS, blk>>>(h1, hf, g2, be2, out);
}

// round 8
// speedup vs baseline: 2.9647x; 2.9647x over previous
#include <cuda_runtime.h>
#include <cstdint>
#include <math.h>

// ---------------------------------------------------------------------------
// Problem constants
// ---------------------------------------------------------------------------
#define BATCH     2
#define SEQ       2048
#define DMODEL    1024
#define FFN_DIM   4096
#define NHEADS    8
#define HEAD_DIM  128
#define RL        4
#define LN_EPS    1e-5f

#define ROWS      (BATCH * SEQ)              // 4096
#define BLD       (BATCH * SEQ * DMODEL)     // 4,194,304
#define HEAD_BLK  (SEQ * HEAD_DIM)           // 262,144
#define NBH       (BATCH * NHEADS)           // 16
#define LL        (SEQ * SEQ)                // 4,194,304 per head

// ---------------------------------------------------------------------------
// Scratch (static device globals)
// ---------------------------------------------------------------------------
__device__ float g_q  [BLD];
__device__ float g_k  [BLD];
__device__ float g_kt [BLD];                 // per-head reshape-transpose of K
__device__ float g_v  [BLD];
__device__ float g_vt [BLD];
__device__ float g_sc [(size_t)NBH * LL];
__device__ float g_ctx[BLD];
__device__ float g_hsa[BLD];
__device__ float g_h1 [BLD];
__device__ float g_mid[(size_t)ROWS * FFN_DIM];
__device__ float g_hf [BLD];
__device__ float g_rq [ROWS * RL];
__device__ float g_rk [ROWS * RL];
__device__ float g_wqt[DMODEL * DMODEL];
__device__ float g_wkt[DMODEL * DMODEL];
__device__ float g_wvt[DMODEL * DMODEL];
__device__ float g_wot[DMODEL * DMODEL];
__device__ float g_w1t[(size_t)DMODEL * FFN_DIM];
__device__ float g_w2t[(size_t)DMODEL * FFN_DIM];

// ---------------------------------------------------------------------------
// Helpers
// ---------------------------------------------------------------------------
__device__ __forceinline__ uint32_t smem_u32(const void* p) {
    uint32_t a;
    asm("{ .reg .u64 t; cvta.to.shared.u64 t, %1; cvt.u32.u64 %0, t; }"
        : "=r"(a) : "l"(p));
    return a;
}
__device__ __forceinline__ uint32_t f2tf32(float x) {
    uint32_t u;
    asm("cvt.rna.tf32.f32 %0, %1;" : "=r"(u) : "f"(x));
    return u;
}

// ---------------------------------------------------------------------------
// TF32 mma.sync GEMM: C[M,N] = alpha * A[M,K](row-major) @ B[N,K](K-major)^T
// + optional rank-4 score bias / bias / relu.
// BM=BN=128, BK=32. 256 threads = 8 warps (2 M x 4 N), warp tile 64x32.
// SMEM: double-buffered A[128][36] + B[128][36] floats = 73728 B.
// ---------------------------------------------------------------------------
#define BKF       32
#define LDS_PAD   36                          // 32 + 4 pad -> conflict-free frags
#define TILE_F    (128 * LDS_PAD)             // floats per tile (4608)
#define BUF_F     (2 * TILE_F)                // floats per buffer pair (9216)
#define SMEM_BYTES (2 * BUF_F * 4)            // 73728

template<bool BIAS, bool RELU, bool SCORE>
__global__ void __launch_bounds__(256, 2)
gemm_mma(const float* __restrict__ A, const float* __restrict__ Bm,
         float* __restrict__ C,
         int M, int N, int K, int lda, int ldb,
         long sA, long sB, long sC,
         const float* __restrict__ bias,
         const float* __restrict__ rq, const float* __restrict__ rk,
         float alpha)
{
    extern __shared__ float smem[];
    const uint32_t sbase = smem_u32(smem);

    const int tid  = threadIdx.x;
    const int warp = tid >> 5;
    const int lane = tid & 31;
    const int wm   = warp & 1;                // 0..1  (M)
    const int wn   = warp >> 1;               // 0..3  (N)
    const int g    = lane >> 2;               // group 0..7
    const int qq   = lane & 3;                // tid-in-group 0..3

    const int z = blockIdx.z;
    A  += (long)z * sA;
    Bm += (long)z * sB;
    C  += (long)z * sC;
    const int bm = blockIdx.y * 128;
    const int bn = blockIdx.x * 128;

    float acc[4][4][4];
#pragma unroll
    for (int i = 0; i < 4; i++)
#pragma unroll
        for (int j = 0; j < 4; j++)
#pragma unroll
            for (int c = 0; c < 4; c++) acc[i][j][c] = 0.f;

    const int KT = K / BKF;

    // ---- async tile loader (A and B tiles, 16B cp.async, coalesced) ----
    auto issue_load = [&](int kt, int buf) {
        const float* Ag = A + (long)bm * lda + kt * BKF;
        const float* Bg = Bm + (long)bn * ldb + kt * BKF;
        const uint32_t da0 = sbase + (uint32_t)(buf * BUF_F) * 4u;
        const uint32_t db0 = da0 + (uint32_t)TILE_F * 4u;
#pragma unroll
        for (int i = 0; i < 4; i++) {
            int lin = tid + i * 256;          // 0..1023
            int r = lin >> 3;                 // 0..127
            int c = lin & 7;                  // 0..7 (float4 chunks)
            uint32_t off = (uint32_t)(r * LDS_PAD + c * 4) * 4u;
            const float* sa = Ag + (long)r * lda + c * 4;
            asm volatile("cp.async.cg.shared.global [%0], [%1], 16;"
                         :: "r"(da0 + off), "l"(sa));
            const float* sb = Bg + (long)r * ldb + c * 4;
            asm volatile("cp.async.cg.shared.global [%0], [%1], 16;"
                         :: "r"(db0 + off), "l"(sb));
        }
        asm volatile("cp.async.commit_group;" ::: "memory");
    };

    issue_load(0, 0);

    for (int kt = 0; kt < KT; kt++) {
        const int buf = kt & 1;
        if (kt + 1 < KT) {
            issue_load(kt + 1, buf ^ 1);
            asm volatile("cp.async.wait_group 1;" ::: "memory");
        } else {
            asm volatile("cp.async.wait_group 0;" ::: "memory");
        }
        __syncthreads();

        const float* Asb = smem + buf * BUF_F;
        const float* Bsb = Asb + TILE_F;

#pragma unroll
        for (int ks = 0; ks < 4; ks++) {
            const int k8 = ks * 8;
            uint32_t af[4][4];
            uint32_t bf[4][2];
#pragma unroll
            for (int mt = 0; mt < 4; mt++) {
                const int rb = wm * 64 + mt * 16;
                af[mt][0] = f2tf32(Asb[(rb + g)     * LDS_PAD + k8 + qq]);
                af[mt][1] = f2tf32(Asb[(rb + g + 8) * LDS_PAD + k8 + qq]);
                af[mt][2] = f2tf32(Asb[(rb + g)     * LDS_PAD + k8 + qq + 4]);
                af[mt][3] = f2tf32(Asb[(rb + g + 8) * LDS_PAD + k8 + qq + 4]);
            }
#pragma unroll
            for (int nt = 0; nt < 4; nt++) {
                const int cb = wn * 32 + nt * 8;
                bf[nt][0] = f2tf32(Bsb[(cb + g) * LDS_PAD + k8 + qq]);
                bf[nt][1] = f2tf32(Bsb[(cb + g) * LDS_PAD + k8 + qq + 4]);
            }
#pragma unroll
            for (int mt = 0; mt < 4; mt++)
#pragma unroll
                for (int nt = 0; nt < 4; nt++) {
                    asm volatile(
                        "mma.sync.aligned.m16n8k8.row.col.f32.tf32.tf32.f32 "
                        "{%0,%1,%2,%3}, {%4,%5,%6,%7}, {%8,%9}, {%0,%1,%2,%3};"
                        : "+f"(acc[mt][nt][0]), "+f"(acc[mt][nt][1]),
                          "+f"(acc[mt][nt][2]), "+f"(acc[mt][nt][3])
                        : "r"(af[mt][0]), "r"(af[mt][1]),
                          "r"(af[mt][2]), "r"(af[mt][3]),
                          "r"(bf[nt][0]), "r"(bf[nt][1]));
                }
        }
        __syncthreads();
    }

    // ---- epilogue ----
    const float* rkb = nullptr;
    const float* rqb = nullptr;
    if (SCORE) {
        const int b = z >> 3;
        rqb = rq + (long)b * M * RL;
        rkb = rk + (long)b * RL * N;
    }

#pragma unroll
    for (int mt = 0; mt < 4; mt++) {
        const int r0 = bm + wm * 64 + mt * 16 + g;
        const int r1 = r0 + 8;
        float p00 = 0.f, p01 = 0.f, p02 = 0.f, p03 = 0.f;
        float p10 = 0.f, p11 = 0.f, p12 = 0.f, p13 = 0.f;
        if (SCORE) {
            p00 = rqb[r0 * RL + 0]; p01 = rqb[r0 * RL + 1];
            p02 = rqb[r0 * RL + 2]; p03 = rqb[r0 * RL + 3];
            p10 = rqb[r1 * RL + 0]; p11 = rqb[r1 * RL + 1];
            p12 = rqb[r1 * RL + 2]; p13 = rqb[r1 * RL + 3];
        }
#pragma unroll
        for (int nt = 0; nt < 4; nt++) {
            const int c = bn + wn * 32 + nt * 8 + 2 * qq;
            float v0 = acc[mt][nt][0] * alpha;
            float v1 = acc[mt][nt][1] * alpha;
            float v2 = acc[mt][nt][2] * alpha;
            float v3 = acc[mt][nt][3] * alpha;
            if (SCORE) {
                float k00 = rkb[c],         k01 = rkb[c + 1];
                float k10 = rkb[N + c],     k11 = rkb[N + c + 1];
                float k20 = rkb[2 * N + c], k21 = rkb[2 * N + c + 1];
                float k30 = rkb[3 * N + c], k31 = rkb[3 * N + c + 1];
                v0 += 0.5f * (p00 * k00 + p01 * k10 + p02 * k20 + p03 * k30);
                v1 += 0.5f * (p00 * k01 + p01 * k11 + p02 * k21 + p03 * k31);
                v2 += 0.5f * (p10 * k00 + p11 * k10 + p12 * k20 + p13 * k30);
                v3 += 0.5f * (p10 * k01 + p11 * k11 + p12 * k21 + p13 * k31);
            }
            if (BIAS) {
                float b0 = bias[c], b1 = bias[c + 1];
                v0 += b0; v1 += b1; v2 += b0; v3 += b1;
            }
            if (RELU) {
                v0 = fmaxf(v0, 0.f); v1 = fmaxf(v1, 0.f);
                v2 = fmaxf(v2, 0.f); v3 = fmaxf(v3, 0.f);
            }
            *(float2*)(C + (long)r0 * N + c) = make_float2(v0, v1);
            *(float2*)(C + (long)r1 * N + c) = make_float2(v2, v3);
        }
    }
}

// ---------------------------------------------------------------------------
// Transpose: out[C,R] = in[R,C]^T  (batched via z with equal stride s)
// ---------------------------------------------------------------------------
__global__ void __launch_bounds__(256)
transpose_kernel(const float* __restrict__ in, float* __restrict__ out,
                 int R, int C, long s)
{
    __shared__ float t[32][33];
    in  += (long)blockIdx.z * s;
    out += (long)blockIdx.z * s;
    const int x  = blockIdx.x * 32 + threadIdx.x;
    const int y0 = blockIdx.y * 32;
#pragma unroll
    for (int i = 0; i < 32; i += 8)
        t[threadIdx.y + i][threadIdx.x] = in[(long)(y0 + threadIdx.y + i) * C + x];
    __syncthreads();
    const int ox  = blockIdx.y * 32 + threadIdx.x;
    const int oy0 = blockIdx.x * 32;
#pragma unroll
    for (int i = 0; i < 32; i += 8)
        out[(long)(oy0 + threadIdx.y + i) * R + ox] = t[threadIdx.x][threadIdx.y + i];
}

// ---------------------------------------------------------------------------
// rank-4 projections
// ---------------------------------------------------------------------------
__global__ void rproj_kernel(const float* __restrict__ rh,
                             const float* __restrict__ Wrk,
                             const float* __restrict__ Wrq,
                             float* __restrict__ rk, float* __restrict__ rq,
                             int n)
{
    int i = blockIdx.x * blockDim.x + threadIdx.x;
    if (i >= n) return;
    float x0 = rh[i * 4 + 0], x1 = rh[i * 4 + 1];
    float x2 = rh[i * 4 + 2], x3 = rh[i * 4 + 3];
#pragma unroll
    for (int j = 0; j < 4; j++) {
        rk[i * 4 + j] = x0 * Wrk[j] + x1 * Wrk[4 + j] + x2 * Wrk[8 + j] + x3 * Wrk[12 + j];
        rq[i * 4 + j] = x0 * Wrq[j] + x1 * Wrq[4 + j] + x2 * Wrq[8 + j] + x3 * Wrq[12 + j];
    }
}

// ---------------------------------------------------------------------------
// Row softmax over SEQ=2048, in place
// ---------------------------------------------------------------------------
__global__ void __launch_bounds__(256)
softmax_kernel(float* __restrict__ S)
{
    float* p = S + (size_t)blockIdx.x * SEQ;
    const int tid = threadIdx.x;
    __shared__ float red[8];

    float v[8];
    float m = -INFINITY;
#pragma unroll
    for (int i = 0; i < 8; i++) { v[i] = p[tid + i * 256]; m = fmaxf(m, v[i]); }
#pragma unroll
    for (int o = 16; o > 0; o >>= 1) m = fmaxf(m, __shfl_xor_sync(0xffffffffu, m, o));
    if ((tid & 31) == 0) red[tid >> 5] = m;
    __syncthreads();
    m = red[0];
#pragma unroll
    for (int w = 1; w < 8; w++) m = fmaxf(m, red[w]);

    float s = 0.f;
#pragma unroll
    for (int i = 0; i < 8; i++) { v[i] = __expf(v[i] - m); s += v[i]; }
#pragma unroll
    for (int o = 16; o > 0; o >>= 1) s += __shfl_xor_sync(0xffffffffu, s, o);
    __syncthreads();
    if ((tid & 31) == 0) red[tid >> 5] = s;
    __syncthreads();
    s = red[0];
#pragma unroll
    for (int w = 1; w < 8; w++) s += red[w];
    const float inv = 1.f / s;
#pragma unroll
    for (int i = 0; i < 8; i++) p[tid + i * 256] = v[i] * inv;
}

// ---------------------------------------------------------------------------
// LayerNorm of (x + y) over D=1024
// ---------------------------------------------------------------------------
__global__ void __launch_bounds__(256)
ln_kernel(const float* __restrict__ x, const float* __restrict__ y,
          const float* __restrict__ g, const float* __restrict__ b,
          float* __restrict__ out)
{
    const size_t base = (size_t)blockIdx.x * DMODEL;
    const int tid = threadIdx.x;
    __shared__ float rs[8], rs2[8];

    float v[4];
    float s = 0.f, s2 = 0.f;
#pragma unroll
    for (int i = 0; i < 4; i++) {
        int c = tid + i * 256;
        v[i] = x[base + c] + y[base + c];
        s  += v[i];
        s2 += v[i] * v[i];
    }
#pragma unroll
    for (int o = 16; o > 0; o >>= 1) {
        s  += __shfl_xor_sync(0xffffffffu, s,  o);
        s2 += __shfl_xor_sync(0xffffffffu, s2, o);
    }
    if ((tid & 31) == 0) { rs[tid >> 5] = s; rs2[tid >> 5] = s2; }
    __syncthreads();
    s = 0.f; s2 = 0.f;
#pragma unroll
    for (int w = 0; w < 8; w++) { s += rs[w]; s2 += rs2[w]; }
    const float mean = s * (1.f / DMODEL);
    const float var  = s2 * (1.f / DMODEL) - mean * mean;
    const float rstd = rsqrtf(var + LN_EPS);
#pragma unroll
    for (int i = 0; i < 4; i++) {
        int c = tid + i * 256;
        out[base + c] = (v[i] - mean) * rstd * g[c] + b[c];
    }
}

// ---------------------------------------------------------------------------
// Launch
// ---------------------------------------------------------------------------
extern "C" void kernel_launch(void* const* d_in, const int* in_sizes, int n_in,
                              void* d_out, int out_size)
{
    const float* h   = (const float*)d_in[0];
    const float* rh  = (const float*)d_in[1];
    const float* Wq  = (const float*)d_in[2];
    const float* Wk  = (const float*)d_in[3];
    const float* Wv  = (const float*)d_in[4];
    const float* Wo  = (const float*)d_in[5];
    const float* Wrk = (const float*)d_in[6];
    const float* Wrq = (const float*)d_in[7];
    const float* W1  = (const float*)d_in[8];
    const float* b1  = (const float*)d_in[9];
    const float* W2  = (const float*)d_in[10];
    const float* b2  = (const float*)d_in[11];
    const float* g1  = (const float*)d_in[12];
    const float* be1 = (const float*)d_in[13];
    const float* g2  = (const float*)d_in[14];
    const float* be2 = (const float*)d_in[15];
    float* out = (float*)d_out;

    float *q, *k, *ktr, *v, *vt, *sc, *ctx, *hsa, *h1, *mid, *hf, *prq, *prk;
    float *wqt, *wkt, *wvt, *wot, *w1t, *w2t;
    cudaGetSymbolAddress((void**)&q,   g_q);
    cudaGetSymbolAddress((void**)&k,   g_k);
    cudaGetSymbolAddress((void**)&ktr, g_kt);
    cudaGetSymbolAddress((void**)&v,   g_v);
    cudaGetSymbolAddress((void**)&vt,  g_vt);
    cudaGetSymbolAddress((void**)&sc,  g_sc);
    cudaGetSymbolAddress((void**)&ctx, g_ctx);
    cudaGetSymbolAddress((void**)&hsa, g_hsa);
    cudaGetSymbolAddress((void**)&h1,  g_h1);
    cudaGetSymbolAddress((void**)&mid, g_mid);
    cudaGetSymbolAddress((void**)&hf,  g_hf);
    cudaGetSymbolAddress((void**)&prq, g_rq);
    cudaGetSymbolAddress((void**)&prk, g_rk);
    cudaGetSymbolAddress((void**)&wqt, g_wqt);
    cudaGetSymbolAddress((void**)&wkt, g_wkt);
    cudaGetSymbolAddress((void**)&wvt, g_wvt);
    cudaGetSymbolAddress((void**)&wot, g_wot);
    cudaGetSymbolAddress((void**)&w1t, g_w1t);
    cudaGetSymbolAddress((void**)&w2t, g_w2t);

    cudaFuncSetAttribute(gemm_mma<false, false, false>,
                         cudaFuncAttributeMaxDynamicSharedMemorySize, SMEM_BYTES);
    cudaFuncSetAttribute(gemm_mma<false, false, true>,
                         cudaFuncAttributeMaxDynamicSharedMemorySize, SMEM_BYTES);
    cudaFuncSetAttribute(gemm_mma<true, true, false>,
                         cudaFuncAttributeMaxDynamicSharedMemorySize, SMEM_BYTES);
    cudaFuncSetAttribute(gemm_mma<true, false, false>,
                         cudaFuncAttributeMaxDynamicSharedMemorySize, SMEM_BYTES);

    const float inv_sqrt_hd = 0.08838834764831845f; // 1/sqrt(128)
    dim3 blk(256);
    dim3 tblk(32, 8);

    // Weight transposes (K-major B operands for all GEMMs)
    transpose_kernel<<<dim3(32, 32, 1),  tblk>>>(Wq, wqt, DMODEL, DMODEL, 0);
    transpose_kernel<<<dim3(32, 32, 1),  tblk>>>(Wk, wkt, DMODEL, DMODEL, 0);
    transpose_kernel<<<dim3(32, 32, 1),  tblk>>>(Wv, wvt, DMODEL, DMODEL, 0);
    transpose_kernel<<<dim3(32, 32, 1),  tblk>>>(Wo, wot, DMODEL, DMODEL, 0);
    transpose_kernel<<<dim3(128, 32, 1), tblk>>>(W1, w1t, DMODEL, FFN_DIM, 0);
    transpose_kernel<<<dim3(32, 128, 1), tblk>>>(W2, w2t, FFN_DIM, DMODEL, 0);

    rproj_kernel<<<(ROWS + 255) / 256, 256>>>(rh, Wrk, Wrq, prk, prq, ROWS);

    // QKV: [4096,1024] @ Wt[1024,1024]^T
    {
        dim3 grid(DMODEL / 128, ROWS / 128, 1);
        gemm_mma<false, false, false><<<grid, blk, SMEM_BYTES>>>(
            h, wqt, q, ROWS, DMODEL, DMODEL, DMODEL, DMODEL,
            0, 0, 0, nullptr, nullptr, nullptr, 1.f);
        gemm_mma<false, false, false><<<grid, blk, SMEM_BYTES>>>(
            h, wkt, k, ROWS, DMODEL, DMODEL, DMODEL, DMODEL,
            0, 0, 0, nullptr, nullptr, nullptr, 1.f);
        gemm_mma<false, false, false><<<grid, blk, SMEM_BYTES>>>(
            h, wvt, v, ROWS, DMODEL, DMODEL, DMODEL, DMODEL,
            0, 0, 0, nullptr, nullptr, nullptr, 1.f);
    }

    // Reference k_t is a RESHAPE (scramble), not a transpose:
    //   k_t[d][m] = kflat_z[d*2048 + m]
    // The score GEMM needs B n-major: B[m][d] = k_t[d][m], i.e. the transpose
    // of the z-block VIEWED as a [128][2048] row-major matrix.
    transpose_kernel<<<dim3(64, 4, NBH), tblk>>>(k, ktr, HEAD_DIM, SEQ, (long)HEAD_BLK);

    // V per head: vt_z[128,2048] = v_z[2048,128]^T  (v_ reshape is natural)
    transpose_kernel<<<dim3(4, 64, NBH), tblk>>>(v, vt, SEQ, HEAD_DIM, (long)HEAD_BLK);

    // scores: Q_z[2048,128] @ ktr_z[2048,128]^T + rank-4 bias, * 1/sqrt(hd)
    {
        dim3 grid(SEQ / 128, SEQ / 128, NBH);
        gemm_mma<false, false, true><<<grid, blk, SMEM_BYTES>>>(
            q, ktr, sc, SEQ, SEQ, HEAD_DIM, HEAD_DIM, HEAD_DIM,
            HEAD_BLK, HEAD_BLK, (long)LL, nullptr, prq, prk, inv_sqrt_hd);
    }

    softmax_kernel<<<NBH * SEQ, blk>>>(sc);

    // context: attn_z[2048,2048] @ vt_z[128,2048]^T
    {
        dim3 grid(1, SEQ / 128, NBH);
        gemm_mma<false, false, false><<<grid, blk, SMEM_BYTES>>>(
            sc, vt, ctx, SEQ, HEAD_DIM, SEQ, SEQ, SEQ,
            (long)LL, (long)HEAD_BLK, (long)HEAD_BLK,
            nullptr, nullptr, nullptr, 1.f);
    }

    // output projection
    {
        dim3 grid(DMODEL / 128, ROWS / 128, 1);
        gemm_mma<false, false, false><<<grid, blk, SMEM_BYTES>>>(
            ctx, wot, hsa, ROWS, DMODEL, DMODEL, DMODEL, DMODEL,
            0, 0, 0, nullptr, nullptr, nullptr, 1.f);
    }

    ln_kernel<<<ROWS, blk>>>(hsa, h, g1, be1, h1);

    // FFN1: [4096,1024] @ W1t[4096,1024]^T + b1, relu
    {
        dim3 grid(FFN_DIM / 128, ROWS / 128, 1);
        gemm_mma<true, true, false><<<grid, blk, SMEM_BYTES>>>(
            h1, w1t, mid, ROWS, FFN_DIM, DMODEL, DMODEL, DMODEL,
            0, 0, 0, b1, nullptr, nullptr, 1.f);
    }

    // FFN2: [4096,4096] @ W2t[1024,4096]^T + b2
    {
        dim3 grid(DMODEL / 128, ROWS / 128, 1);
        gemm_mma<true, false, false><<<grid, blk, SMEM_BYTES>>>(
            mid, w2t, hf, ROWS, DMODEL, FFN_DIM, FFN_DIM, FFN_DIM,
            0, 0, 0, b2, nullptr, nullptr, 1.f);
    }

    ln_kernel<<<ROWS, blk>>>(h1, hf, g2, be2, out);
}

// round 9
// speedup vs baseline: 3.2142x; 1.0842x over previous
#include <cuda_runtime.h>
#include <cstdint>
#include <math.h>

// ---------------------------------------------------------------------------
// Problem constants
// ---------------------------------------------------------------------------
#define BATCH     2
#define SEQ       2048
#define DMODEL    1024
#define FFN_DIM   4096
#define NHEADS    8
#define HEAD_DIM  128
#define RL        4
#define LN_EPS    1e-5f

#define ROWS      (BATCH * SEQ)              // 4096
#define BLD       (BATCH * SEQ * DMODEL)     // 4,194,304
#define HEAD_BLK  (SEQ * HEAD_DIM)           // 262,144
#define NBH       (BATCH * NHEADS)           // 16
#define LL        (SEQ * SEQ)                // 4,194,304 per head

// ---------------------------------------------------------------------------
// Scratch (static device globals)
// ---------------------------------------------------------------------------
__device__ float g_q  [BLD];
__device__ float g_k  [BLD];
__device__ float g_kt [BLD];
__device__ float g_v  [BLD];
__device__ float g_vt [BLD];
__device__ float g_sc [(size_t)NBH * LL];
__device__ float g_ctx[BLD];
__device__ float g_hsa[BLD];
__device__ float g_h1 [BLD];
__device__ float g_mid[(size_t)ROWS * FFN_DIM];
__device__ float g_hf [BLD];
__device__ float g_rq [ROWS * RL];
__device__ float g_rk [ROWS * RL];
__device__ float g_wqkvt[(size_t)3 * DMODEL * DMODEL];   // packed [3072][1024]
__device__ float g_wot[DMODEL * DMODEL];
__device__ float g_w1t[(size_t)DMODEL * FFN_DIM];
__device__ float g_w2t[(size_t)DMODEL * FFN_DIM];

// ---------------------------------------------------------------------------
// Helpers
// ---------------------------------------------------------------------------
__device__ __forceinline__ uint32_t smem_u32(const void* p) {
    uint32_t a;
    asm("{ .reg .u64 t; cvta.to.shared.u64 t, %1; cvt.u32.u64 %0, t; }"
        : "=r"(a) : "l"(p));
    return a;
}
__device__ __forceinline__ uint32_t f2tf32(uint32_t xbits) {
    uint32_t u;
    asm("cvt.rna.tf32.f32 %0, %1;" : "=r"(u) : "f"(__uint_as_float(xbits)));
    return u;
}
__device__ __forceinline__ void ldsm_x4(uint32_t& r0, uint32_t& r1,
                                        uint32_t& r2, uint32_t& r3, uint32_t a) {
    asm volatile("ldmatrix.sync.aligned.m8n8.x4.shared.b16 {%0,%1,%2,%3}, [%4];"
                 : "=r"(r0), "=r"(r1), "=r"(r2), "=r"(r3) : "r"(a));
}

// ---------------------------------------------------------------------------
// TF32 mma.sync GEMM: C[M,N] = alpha * A[M,K](row-major) @ B[N,K](K-major)^T
// + optional rank-4 score bias / bias / relu / 3-way column-split output.
// BM=BN=128, BK=32. 8 warps (2 M x 4 N), warp tile 64x32, ldmatrix frags.
// ---------------------------------------------------------------------------
#define BKF       32
#define LDS_PAD   36                          // row stride 144B, conflict-free
#define TILE_F    (128 * LDS_PAD)
#define BUF_F     (2 * TILE_F)
#define SMEM_BYTES (2 * BUF_F * 4)            // 73728

template<bool BIAS, bool RELU, bool SCORE, bool SPLIT>
__global__ void __launch_bounds__(256, 2)
gemm_mma(const float* __restrict__ A, const float* __restrict__ Bm,
         float* __restrict__ C, float* __restrict__ C1, float* __restrict__ C2,
         int M, int N, int K, int lda, int ldb, int ldc,
         long sA, long sB, long sC,
         const float* __restrict__ bias,
         const float* __restrict__ rq, const float* __restrict__ rk,
         float alpha)
{
    extern __shared__ float smem[];
    const uint32_t sbase = smem_u32(smem);

    const int tid  = threadIdx.x;
    const int warp = tid >> 5;
    const int lane = tid & 31;
    const int wm   = warp & 1;                // 0..1  (M)
    const int wn   = warp >> 1;               // 0..3  (N)
    const int g    = lane >> 2;               // group 0..7
    const int qq   = lane & 3;                // tid-in-group

    const int z = blockIdx.z;
    A  += (long)z * sA;
    Bm += (long)z * sB;
    const int bm = blockIdx.y * 128;
    const int bn = blockIdx.x * 128;

    // output base / local column (3-way split for fused QKV)
    float* Cd;
    int cl;
    if (SPLIT) {
        const int sec = bn >> 10;
        Cd = (sec == 0) ? C : ((sec == 1) ? C1 : C2);
        cl = bn & 1023;
    } else {
        Cd = C + (long)z * sC;
        cl = bn;
    }

    // ldmatrix per-lane chunk offsets (bytes)
    const uint32_t a_off = (uint32_t)(((wm * 64 + ((lane >> 3) & 1) * 8 + (lane & 7))
                                      * LDS_PAD + (lane >> 4) * 4) * 4);
    const uint32_t b_off = (uint32_t)(((wn * 32 + ((lane >> 4) & 1) * 8 + (lane & 7))
                                      * LDS_PAD + ((lane >> 3) & 1) * 4) * 4);

    float acc[4][4][4];
#pragma unroll
    for (int i = 0; i < 4; i++)
#pragma unroll
        for (int j = 0; j < 4; j++)
#pragma unroll
            for (int c = 0; c < 4; c++) acc[i][j][c] = 0.f;

    const int KT = K / BKF;

    auto issue_load = [&](int kt, int buf) {
        const float* Ag = A + (long)bm * lda + kt * BKF;
        const float* Bg = Bm + (long)bn * ldb + kt * BKF;
        const uint32_t da0 = sbase + (uint32_t)(buf * BUF_F) * 4u;
        const uint32_t db0 = da0 + (uint32_t)TILE_F * 4u;
#pragma unroll
        for (int i = 0; i < 4; i++) {
            int lin = tid + i * 256;
            int r = lin >> 3, c = lin & 7;
            uint32_t off = (uint32_t)(r * LDS_PAD + c * 4) * 4u;
            asm volatile("cp.async.cg.shared.global [%0], [%1], 16;"
                         :: "r"(da0 + off), "l"(Ag + (long)r * lda + c * 4));
            asm volatile("cp.async.cg.shared.global [%0], [%1], 16;"
                         :: "r"(db0 + off), "l"(Bg + (long)r * ldb + c * 4));
        }
        asm volatile("cp.async.commit_group;" ::: "memory");
    };

    issue_load(0, 0);

    for (int kt = 0; kt < KT; kt++) {
        const int buf = kt & 1;
        if (kt + 1 < KT) {
            issue_load(kt + 1, buf ^ 1);
            asm volatile("cp.async.wait_group 1;" ::: "memory");
        } else {
            asm volatile("cp.async.wait_group 0;" ::: "memory");
        }
        __syncthreads();

        const uint32_t Au = sbase + (uint32_t)(buf * BUF_F) * 4u;
        const uint32_t Bu = Au + (uint32_t)TILE_F * 4u;

#pragma unroll
        for (int ks = 0; ks < 4; ks++) {
            const uint32_t k8b = (uint32_t)(ks * 32);   // 8 floats = 32 bytes
            uint32_t af[4][4];
            uint32_t bf[4][2];
#pragma unroll
            for (int mt = 0; mt < 4; mt++)
                ldsm_x4(af[mt][0], af[mt][1], af[mt][2], af[mt][3],
                        Au + a_off + (uint32_t)(mt * 16 * LDS_PAD * 4) + k8b);
            ldsm_x4(bf[0][0], bf[0][1], bf[1][0], bf[1][1], Bu + b_off + k8b);
            ldsm_x4(bf[2][0], bf[2][1], bf[3][0], bf[3][1],
                    Bu + b_off + (uint32_t)(16 * LDS_PAD * 4) + k8b);
#pragma unroll
            for (int mt = 0; mt < 4; mt++)
#pragma unroll
                for (int r = 0; r < 4; r++) af[mt][r] = f2tf32(af[mt][r]);
#pragma unroll
            for (int nt = 0; nt < 4; nt++) {
                bf[nt][0] = f2tf32(bf[nt][0]);
                bf[nt][1] = f2tf32(bf[nt][1]);
            }
#pragma unroll
            for (int mt = 0; mt < 4; mt++)
#pragma unroll
                for (int nt = 0; nt < 4; nt++) {
                    asm volatile(
                        "mma.sync.aligned.m16n8k8.row.col.f32.tf32.tf32.f32 "
                        "{%0,%1,%2,%3}, {%4,%5,%6,%7}, {%8,%9}, {%0,%1,%2,%3};"
                        : "+f"(acc[mt][nt][0]), "+f"(acc[mt][nt][1]),
                          "+f"(acc[mt][nt][2]), "+f"(acc[mt][nt][3])
                        : "r"(af[mt][0]), "r"(af[mt][1]),
                          "r"(af[mt][2]), "r"(af[mt][3]),
                          "r"(bf[nt][0]), "r"(bf[nt][1]));
                }
        }
        __syncthreads();
    }

    // ---- epilogue ----
    const float* rkb = nullptr;
    const float* rqb = nullptr;
    if (SCORE) {
        const int b = z >> 3;
        rqb = rq + (long)b * M * RL;
        rkb = rk + (long)b * RL * N;
    }

#pragma unroll
    for (int mt = 0; mt < 4; mt++) {
        const int r0 = bm + wm * 64 + mt * 16 + g;
        const int r1 = r0 + 8;
        float p00 = 0.f, p01 = 0.f, p02 = 0.f, p03 = 0.f;
        float p10 = 0.f, p11 = 0.f, p12 = 0.f, p13 = 0.f;
        if (SCORE) {
            p00 = rqb[r0 * RL + 0]; p01 = rqb[r0 * RL + 1];
            p02 = rqb[r0 * RL + 2]; p03 = rqb[r0 * RL + 3];
            p10 = rqb[r1 * RL + 0]; p11 = rqb[r1 * RL + 1];
            p12 = rqb[r1 * RL + 2]; p13 = rqb[r1 * RL + 3];
        }
#pragma unroll
        for (int nt = 0; nt < 4; nt++) {
            const int co = wn * 32 + nt * 8 + 2 * qq;    // 0..127 within tile
            const int c  = bn + co;                      // global column
            float v0 = acc[mt][nt][0] * alpha;
            float v1 = acc[mt][nt][1] * alpha;
            float v2 = acc[mt][nt][2] * alpha;
            float v3 = acc[mt][nt][3] * alpha;
            if (SCORE) {
                float k00 = rkb[c],         k01 = rkb[c + 1];
                float k10 = rkb[N + c],     k11 = rkb[N + c + 1];
                float k20 = rkb[2 * N + c], k21 = rkb[2 * N + c + 1];
                float k30 = rkb[3 * N + c], k31 = rkb[3 * N + c + 1];
                v0 += 0.5f * (p00 * k00 + p01 * k10 + p02 * k20 + p03 * k30);
                v1 += 0.5f * (p00 * k01 + p01 * k11 + p02 * k21 + p03 * k31);
                v2 += 0.5f * (p10 * k00 + p11 * k10 + p12 * k20 + p13 * k30);
                v3 += 0.5f * (p10 * k01 + p11 * k11 + p12 * k21 + p13 * k31);
            }
            if (BIAS) {
                float b0 = bias[c], b1 = bias[c + 1];
                v0 += b0; v1 += b1; v2 += b0; v3 += b1;
            }
            if (RELU) {
                v0 = fmaxf(v0, 0.f); v1 = fmaxf(v1, 0.f);
                v2 = fmaxf(v2, 0.f); v3 = fmaxf(v3, 0.f);
            }
            *(float2*)(Cd + (long)r0 * ldc + cl + co) = make_float2(v0, v1);
            *(float2*)(Cd + (long)r1 * ldc + cl + co) = make_float2(v2, v3);
        }
    }
}

// ---------------------------------------------------------------------------
// Transpose: out[C,R] = in[R,C]^T  (batched via z with equal stride s)
// ---------------------------------------------------------------------------
__global__ void __launch_bounds__(256)
transpose_kernel(const float* __restrict__ in, float* __restrict__ out,
                 int R, int C, long s)
{
    __shared__ float t[32][33];
    in  += (long)blockIdx.z * s;
    out += (long)blockIdx.z * s;
    const int x  = blockIdx.x * 32 + threadIdx.x;
    const int y0 = blockIdx.y * 32;
#pragma unroll
    for (int i = 0; i < 32; i += 8)
        t[threadIdx.y + i][threadIdx.x] = in[(long)(y0 + threadIdx.y + i) * C + x];
    __syncthreads();
    const int ox  = blockIdx.y * 32 + threadIdx.x;
    const int oy0 = blockIdx.x * 32;
#pragma unroll
    for (int i = 0; i < 32; i += 8)
        out[(long)(oy0 + threadIdx.y + i) * R + ox] = t[threadIdx.x][threadIdx.y + i];
}

// 3-source 1024x1024 transpose into packed [3072][1024] buffer (z = source)
__global__ void __launch_bounds__(256)
transpose3_kernel(const float* __restrict__ in0, const float* __restrict__ in1,
                  const float* __restrict__ in2, float* __restrict__ out)
{
    __shared__ float t[32][33];
    const float* in = (blockIdx.z == 0) ? in0 : ((blockIdx.z == 1) ? in1 : in2);
    out += (long)blockIdx.z * DMODEL * DMODEL;
    const int x  = blockIdx.x * 32 + threadIdx.x;
    const int y0 = blockIdx.y * 32;
#pragma unroll
    for (int i = 0; i < 32; i += 8)
        t[threadIdx.y + i][threadIdx.x] = in[(long)(y0 + threadIdx.y + i) * DMODEL + x];
    __syncthreads();
    const int ox  = blockIdx.y * 32 + threadIdx.x;
    const int oy0 = blockIdx.x * 32;
#pragma unroll
    for (int i = 0; i < 32; i += 8)
        out[(long)(oy0 + threadIdx.y + i) * DMODEL + ox] = t[threadIdx.x][threadIdx.y + i];
}

// ---------------------------------------------------------------------------
// rank-4 projections
// ---------------------------------------------------------------------------
__global__ void rproj_kernel(const float* __restrict__ rh,
                             const float* __restrict__ Wrk,
                             const float* __restrict__ Wrq,
                             float* __restrict__ rk, float* __restrict__ rq,
                             int n)
{
    int i = blockIdx.x * blockDim.x + threadIdx.x;
    if (i >= n) return;
    float x0 = rh[i * 4 + 0], x1 = rh[i * 4 + 1];
    float x2 = rh[i * 4 + 2], x3 = rh[i * 4 + 3];
#pragma unroll
    for (int j = 0; j < 4; j++) {
        rk[i * 4 + j] = x0 * Wrk[j] + x1 * Wrk[4 + j] + x2 * Wrk[8 + j] + x3 * Wrk[12 + j];
        rq[i * 4 + j] = x0 * Wrq[j] + x1 * Wrq[4 + j] + x2 * Wrq[8 + j] + x3 * Wrq[12 + j];
    }
}

// ---------------------------------------------------------------------------
// Row softmax over SEQ=2048, in place, float4 vectorized
// ---------------------------------------------------------------------------
__global__ void __launch_bounds__(256)
softmax_kernel(float* __restrict__ S)
{
    float4* p = (float4*)(S + (size_t)blockIdx.x * SEQ);
    const int tid = threadIdx.x;
    __shared__ float red[8];

    float4 va = p[tid], vb = p[tid + 256];
    float m = fmaxf(fmaxf(fmaxf(va.x, va.y), fmaxf(va.z, va.w)),
                    fmaxf(fmaxf(vb.x, vb.y), fmaxf(vb.z, vb.w)));
#pragma unroll
    for (int o = 16; o > 0; o >>= 1) m = fmaxf(m, __shfl_xor_sync(0xffffffffu, m, o));
    if ((tid & 31) == 0) red[tid >> 5] = m;
    __syncthreads();
    m = red[0];
#pragma unroll
    for (int w = 1; w < 8; w++) m = fmaxf(m, red[w]);

    va.x = __expf(va.x - m); va.y = __expf(va.y - m);
    va.z = __expf(va.z - m); va.w = __expf(va.w - m);
    vb.x = __expf(vb.x - m); vb.y = __expf(vb.y - m);
    vb.z = __expf(vb.z - m); vb.w = __expf(vb.w - m);
    float s = va.x + va.y + va.z + va.w + vb.x + vb.y + vb.z + vb.w;
#pragma unroll
    for (int o = 16; o > 0; o >>= 1) s += __shfl_xor_sync(0xffffffffu, s, o);
    __syncthreads();
    if ((tid & 31) == 0) red[tid >> 5] = s;
    __syncthreads();
    s = red[0];
#pragma unroll
    for (int w = 1; w < 8; w++) s += red[w];
    const float inv = 1.f / s;
    va.x *= inv; va.y *= inv; va.z *= inv; va.w *= inv;
    vb.x *= inv; vb.y *= inv; vb.z *= inv; vb.w *= inv;
    p[tid] = va; p[tid + 256] = vb;
}

// ---------------------------------------------------------------------------
// LayerNorm of (x + y) over D=1024, float4 vectorized
// ---------------------------------------------------------------------------
__global__ void __launch_bounds__(256)
ln_kernel(const float* __restrict__ x, const float* __restrict__ y,
          const float* __restrict__ g, const float* __restrict__ b,
          float* __restrict__ out)
{
    const size_t base4 = (size_t)blockIdx.x * (DMODEL / 4);
    const int tid = threadIdx.x;
    __shared__ float rs[8], rs2[8];

    float4 vx = ((const float4*)x)[base4 + tid];
    float4 vy = ((const float4*)y)[base4 + tid];
    float4 v = make_float4(vx.x + vy.x, vx.y + vy.y, vx.z + vy.z, vx.w + vy.w);
    float s  = v.x + v.y + v.z + v.w;
    float s2 = v.x * v.x + v.y * v.y + v.z * v.z + v.w * v.w;
#pragma unroll
    for (int o = 16; o > 0; o >>= 1) {
        s  += __shfl_xor_sync(0xffffffffu, s,  o);
        s2 += __shfl_xor_sync(0xffffffffu, s2, o);
    }
    if ((tid & 31) == 0) { rs[tid >> 5] = s; rs2[tid >> 5] = s2; }
    __syncthreads();
    s = 0.f; s2 = 0.f;
#pragma unroll
    for (int w = 0; w < 8; w++) { s += rs[w]; s2 += rs2[w]; }
    const float mean = s * (1.f / DMODEL);
    const float var  = s2 * (1.f / DMODEL) - mean * mean;
    const float rstd = rsqrtf(var + LN_EPS);
    float4 vg = ((const float4*)g)[tid];
    float4 vb = ((const float4*)b)[tid];
    float4 o4;
    o4.x = (v.x - mean) * rstd * vg.x + vb.x;
    o4.y = (v.y - mean) * rstd * vg.y + vb.y;
    o4.z = (v.z - mean) * rstd * vg.z + vb.z;
    o4.w = (v.w - mean) * rstd * vg.w + vb.w;
    ((float4*)out)[base4 + tid] = o4;
}

// ---------------------------------------------------------------------------
// Launch
// ---------------------------------------------------------------------------
extern "C" void kernel_launch(void* const* d_in, const int* in_sizes, int n_in,
                              void* d_out, int out_size)
{
    const float* h   = (const float*)d_in[0];
    const float* rh  = (const float*)d_in[1];
    const float* Wq  = (const float*)d_in[2];
    const float* Wk  = (const float*)d_in[3];
    const float* Wv  = (const float*)d_in[4];
    const float* Wo  = (const float*)d_in[5];
    const float* Wrk = (const float*)d_in[6];
    const float* Wrq = (const float*)d_in[7];
    const float* W1  = (const float*)d_in[8];
    const float* b1  = (const float*)d_in[9];
    const float* W2  = (const float*)d_in[10];
    const float* b2  = (const float*)d_in[11];
    const float* g1  = (const float*)d_in[12];
    const float* be1 = (const float*)d_in[13];
    const float* g2  = (const float*)d_in[14];
    const float* be2 = (const float*)d_in[15];
    float* out = (float*)d_out;

    float *q, *k, *ktr, *v, *vt, *sc, *ctx, *hsa, *h1, *mid, *hf, *prq, *prk;
    float *wqkvt, *wot, *w1t, *w2t;
    cudaGetSymbolAddress((void**)&q,     g_q);
    cudaGetSymbolAddress((void**)&k,     g_k);
    cudaGetSymbolAddress((void**)&ktr,   g_kt);
    cudaGetSymbolAddress((void**)&v,     g_v);
    cudaGetSymbolAddress((void**)&vt,    g_vt);
    cudaGetSymbolAddress((void**)&sc,    g_sc);
    cudaGetSymbolAddress((void**)&ctx,   g_ctx);
    cudaGetSymbolAddress((void**)&hsa,   g_hsa);
    cudaGetSymbolAddress((void**)&h1,    g_h1);
    cudaGetSymbolAddress((void**)&mid,   g_mid);
    cudaGetSymbolAddress((void**)&hf,    g_hf);
    cudaGetSymbolAddress((void**)&prq,   g_rq);
    cudaGetSymbolAddress((void**)&prk,   g_rk);
    cudaGetSymbolAddress((void**)&wqkvt, g_wqkvt);
    cudaGetSymbolAddress((void**)&wot,   g_wot);
    cudaGetSymbolAddress((void**)&w1t,   g_w1t);
    cudaGetSymbolAddress((void**)&w2t,   g_w2t);

    cudaFuncSetAttribute(gemm_mma<false, false, false, false>,
                         cudaFuncAttributeMaxDynamicSharedMemorySize, SMEM_BYTES);
    cudaFuncSetAttribute(gemm_mma<false, false, false, true>,
                         cudaFuncAttributeMaxDynamicSharedMemorySize, SMEM_BYTES);
    cudaFuncSetAttribute(gemm_mma<false, false, true, false>,
                         cudaFuncAttributeMaxDynamicSharedMemorySize, SMEM_BYTES);
    cudaFuncSetAttribute(gemm_mma<true, true, false, false>,
                         cudaFuncAttributeMaxDynamicSharedMemorySize, SMEM_BYTES);
    cudaFuncSetAttribute(gemm_mma<true, false, false, false>,
                         cudaFuncAttributeMaxDynamicSharedMemorySize, SMEM_BYTES);

    const float inv_sqrt_hd = 0.08838834764831845f; // 1/sqrt(128)
    dim3 blk(256);
    dim3 tblk(32, 8);

    // Weight transposes (K-major B operands)
    transpose3_kernel<<<dim3(32, 32, 3), tblk>>>(Wq, Wk, Wv, wqkvt);
    transpose_kernel<<<dim3(32, 32, 1),  tblk>>>(Wo, wot, DMODEL, DMODEL, 0);
    transpose_kernel<<<dim3(128, 32, 1), tblk>>>(W1, w1t, DMODEL, FFN_DIM, 0);
    transpose_kernel<<<dim3(32, 128, 1), tblk>>>(W2, w2t, FFN_DIM, DMODEL, 0);

    rproj_kernel<<<(ROWS + 255) / 256, 256>>>(rh, Wrk, Wrq, prk, prq, ROWS);

    // Fused QKV: [4096,1024] @ wqkvt[3072,1024]^T -> split into q|k|v
    {
        dim3 grid(3 * DMODEL / 128, ROWS / 128, 1);
        gemm_mma<false, false, false, true><<<grid, blk, SMEM_BYTES>>>(
            h, wqkvt, q, k, v, ROWS, 3 * DMODEL, DMODEL,
            DMODEL, DMODEL, DMODEL, 0, 0, 0, nullptr, nullptr, nullptr, 1.f);
    }

    // k_t is a flat reshape: score-B operand = transpose of the z-block
    // viewed as a [128][2048] row-major matrix.
    transpose_kernel<<<dim3(64, 4, NBH), tblk>>>(k, ktr, HEAD_DIM, SEQ, (long)HEAD_BLK);
    // vt_z[128,2048] = v_z[2048,128]^T
    transpose_kernel<<<dim3(4, 64, NBH), tblk>>>(v, vt, SEQ, HEAD_DIM, (long)HEAD_BLK);

    // scores: Q_z[2048,128] @ ktr_z[2048,128]^T + rank-4 bias
    {
        dim3 grid(SEQ / 128, SEQ / 128, NBH);
        gemm_mma<false, false, true, false><<<grid, blk, SMEM_BYTES>>>(
            q, ktr, sc, nullptr, nullptr, SEQ, SEQ, HEAD_DIM,
            HEAD_DIM, HEAD_DIM, SEQ, HEAD_BLK, HEAD_BLK, (long)LL,
            nullptr, prq, prk, inv_sqrt_hd);
    }

    softmax_kernel<<<NBH * SEQ, blk>>>(sc);

    // context: attn_z[2048,2048] @ vt_z[128,2048]^T
    {
        dim3 grid(1, SEQ / 128, NBH);
        gemm_mma<false, false, false, false><<<grid, blk, SMEM_BYTES>>>(
            sc, vt, ctx, nullptr, nullptr, SEQ, HEAD_DIM, SEQ,
            SEQ, SEQ, HEAD_DIM, (long)LL, (long)HEAD_BLK, (long)HEAD_BLK,
            nullptr, nullptr, nullptr, 1.f);
    }

    // output projection
    {
        dim3 grid(DMODEL / 128, ROWS / 128, 1);
        gemm_mma<false, false, false, false><<<grid, blk, SMEM_BYTES>>>(
            ctx, wot, hsa, nullptr, nullptr, ROWS, DMODEL, DMODEL,
            DMODEL, DMODEL, DMODEL, 0, 0, 0, nullptr, nullptr, nullptr, 1.f);
    }

    ln_kernel<<<ROWS, blk>>>(hsa, h, g1, be1, h1);

    // FFN1: + b1, relu
    {
        dim3 grid(FFN_DIM / 128, ROWS / 128, 1);
        gemm_mma<true, true, false, false><<<grid, blk, SMEM_BYTES>>>(
            h1, w1t, mid, nullptr, nullptr, ROWS, FFN_DIM, DMODEL,
            DMODEL, DMODEL, FFN_DIM, 0, 0, 0, b1, nullptr, nullptr, 1.f);
    }

    // FFN2: + b2
    {
        dim3 grid(DMODEL / 128, ROWS / 128, 1);
        gemm_mma<true, false, false, false><<<grid, blk, SMEM_BYTES>>>(
            mid, w2t, hf, nullptr, nullptr, ROWS, DMODEL, FFN_DIM,
            FFN_DIM, FFN_DIM, DMODEL, 0, 0, 0, b2, nullptr, nullptr, 1.f);
    }

    ln_kernel<<<ROWS, blk>>>(h1, hf, g2, be2, out);
}